// round 1
// baseline (speedup 1.0000x reference)
#include <cuda_runtime.h>
#include <math.h>

// ---------------- scratch (static __device__; no allocations allowed) ----------------
__device__ float g_act1[256 * 10 * 48 * 48];   // conv1 output, pooled+relu
__device__ float g_act2[256 * 20 * 22 * 22];   // conv2 output, pooled+relu == FC0 input [256,9680]
__device__ float g_h0[256 * 2048];
__device__ float g_h1[256 * 1024];
__device__ float g_fc2[256 * 142];

// =====================================================================
// conv1 (1->10, 5x5 VALID) + bias + maxpool2 + relu, one block per image
// =====================================================================
__global__ void __launch_bounds__(256) conv1_kernel(const float* __restrict__ x,
                                                    const float* __restrict__ w,
                                                    const float* __restrict__ bias)
{
    __shared__ float sx[10000];   // 100x100 image
    __shared__ float sw[250];     // 10 x 25
    __shared__ float sb[10];
    const int b   = blockIdx.x;
    const int tid = threadIdx.x;
    const float* xin = x + b * 10000;
    for (int i = tid; i < 10000; i += 256) sx[i] = xin[i];
    if (tid < 250) sw[tid] = w[tid];
    if (tid < 10)  sb[tid] = bias[tid];
    __syncthreads();

    // tasks: 10 oc * (24x24) 2x2-pooled tiles = 5760
    for (int task = tid; task < 5760; task += 256) {
        const int oc = task / 576;
        const int t  = task % 576;
        const int ti = t / 24, tj = t % 24;

        float wr[25];
        #pragma unroll
        for (int q = 0; q < 25; q++) wr[q] = sw[oc * 25 + q];

        float xr[8][8];
        #pragma unroll
        for (int r = 0; r < 8; r++)
            #pragma unroll
            for (int c = 0; c < 8; c++)
                xr[r][c] = sx[(4 * ti + r) * 100 + 4 * tj + c];

        float acc[4][4];
        #pragma unroll
        for (int r = 0; r < 4; r++)
            #pragma unroll
            for (int c = 0; c < 4; c++) acc[r][c] = 0.f;

        #pragma unroll
        for (int ki = 0; ki < 5; ki++)
            #pragma unroll
            for (int kj = 0; kj < 5; kj++) {
                const float wv = wr[ki * 5 + kj];
                #pragma unroll
                for (int r = 0; r < 4; r++)
                    #pragma unroll
                    for (int c = 0; c < 4; c++)
                        acc[r][c] = fmaf(xr[r + ki][c + kj], wv, acc[r][c]);
            }

        const float bb = sb[oc];
        float* outp = g_act1 + ((b * 10 + oc) * 48) * 48;
        #pragma unroll
        for (int pi = 0; pi < 2; pi++)
            #pragma unroll
            for (int pj = 0; pj < 2; pj++) {
                float m = fmaxf(fmaxf(acc[2*pi][2*pj],   acc[2*pi][2*pj+1]),
                                fmaxf(acc[2*pi+1][2*pj], acc[2*pi+1][2*pj+1]));
                m = fmaxf(m + bb, 0.f);
                outp[(2 * ti + pi) * 48 + 2 * tj + pj] = m;
            }
    }
}

// =====================================================================
// conv2 (10->20, 5x5 VALID) + bias + maxpool2 + relu, one block per image
// dynamic smem: input 10x48x48 (92160B) + weights 20x10x25 (20000B) + bias
// =====================================================================
#define CONV2_SMEM_BYTES ((23040 + 5000 + 32) * 4)

__global__ void __launch_bounds__(256) conv2_kernel(const float* __restrict__ w,
                                                    const float* __restrict__ bias)
{
    extern __shared__ float smem[];
    float* sx = smem;               // 23040
    float* sw = smem + 23040;       // 5000
    float* sb = sw + 5000;          // 20
    const int b   = blockIdx.x;
    const int tid = threadIdx.x;
    const float* xin = g_act1 + b * 23040;
    for (int i = tid; i < 23040; i += 256) sx[i] = xin[i];
    for (int i = tid; i < 5000; i += 256)  sw[i] = w[i];
    if (tid < 20) sb[tid] = bias[tid];
    __syncthreads();

    // tasks: 20 oc * (11x11) 2x2-pooled tiles = 2420
    for (int task = tid; task < 2420; task += 256) {
        const int oc = task / 121;
        const int t  = task % 121;
        const int ti = t / 11, tj = t % 11;

        float acc[4][4];
        #pragma unroll
        for (int r = 0; r < 4; r++)
            #pragma unroll
            for (int c = 0; c < 4; c++) acc[r][c] = 0.f;

        for (int ic = 0; ic < 10; ic++) {
            float wr[25];
            #pragma unroll
            for (int q = 0; q < 25; q++) wr[q] = sw[(oc * 10 + ic) * 25 + q];

            float xr[8][8];
            #pragma unroll
            for (int r = 0; r < 8; r++)
                #pragma unroll
                for (int c = 0; c < 8; c++)
                    xr[r][c] = sx[ic * 2304 + (4 * ti + r) * 48 + 4 * tj + c];

            #pragma unroll
            for (int ki = 0; ki < 5; ki++)
                #pragma unroll
                for (int kj = 0; kj < 5; kj++) {
                    const float wv = wr[ki * 5 + kj];
                    #pragma unroll
                    for (int r = 0; r < 4; r++)
                        #pragma unroll
                        for (int c = 0; c < 4; c++)
                            acc[r][c] = fmaf(xr[r + ki][c + kj], wv, acc[r][c]);
                }
        }

        const float bb = sb[oc];
        float* outp = g_act2 + ((b * 20 + oc) * 22) * 22;
        #pragma unroll
        for (int pi = 0; pi < 2; pi++)
            #pragma unroll
            for (int pj = 0; pj < 2; pj++) {
                float m = fmaxf(fmaxf(acc[2*pi][2*pj],   acc[2*pi][2*pj+1]),
                                fmaxf(acc[2*pi+1][2*pj], acc[2*pi+1][2*pj+1]));
                m = fmaxf(m + bb, 0.f);
                outp[(2 * ti + pi) * 22 + 2 * tj + pj] = m;
            }
    }
}

// =====================================================================
// Tiled SGEMM  C[M,N] = act( A[M,K] @ B[K,N] + bias )
// BM=BN=64, BK=16, 256 threads, 4x4 micro-tile. M,N,K multiples of 64/64/16.
// =====================================================================
__global__ void __launch_bounds__(256) gemm_bias_act(const float* __restrict__ A,
                                                     const float* __restrict__ B,
                                                     const float* __restrict__ bias,
                                                     float* __restrict__ C,
                                                     int N, int K, int doTanh)
{
    __shared__ float As[16][64];   // transposed A tile: As[k][m]
    __shared__ float Bs[16][64];

    const int tid = threadIdx.x;
    const int tx = tid & 15;       // n
    const int ty = tid >> 4;       // m
    const int blockM = blockIdx.y * 64;
    const int blockN = blockIdx.x * 64;

    const int aRow = tid >> 2;            // 0..63
    const int aK4  = (tid & 3) * 4;       // 0,4,8,12
    const int bRow = tid >> 4;            // 0..15
    const int bCol = (tid & 15) * 4;      // 0..60

    float acc[4][4];
    #pragma unroll
    for (int i = 0; i < 4; i++)
        #pragma unroll
        for (int j = 0; j < 4; j++) acc[i][j] = 0.f;

    for (int k0 = 0; k0 < K; k0 += 16) {
        const float4 av = *(const float4*)&A[(blockM + aRow) * K + k0 + aK4];
        As[aK4 + 0][aRow] = av.x;
        As[aK4 + 1][aRow] = av.y;
        As[aK4 + 2][aRow] = av.z;
        As[aK4 + 3][aRow] = av.w;
        *(float4*)&Bs[bRow][bCol] = *(const float4*)&B[(k0 + bRow) * N + blockN + bCol];
        __syncthreads();

        #pragma unroll
        for (int k = 0; k < 16; k++) {
            const float4 aa = *(const float4*)&As[k][ty * 4];
            const float4 bb = *(const float4*)&Bs[k][tx * 4];
            const float ar[4] = {aa.x, aa.y, aa.z, aa.w};
            const float br[4] = {bb.x, bb.y, bb.z, bb.w};
            #pragma unroll
            for (int i = 0; i < 4; i++)
                #pragma unroll
                for (int j = 0; j < 4; j++)
                    acc[i][j] = fmaf(ar[i], br[j], acc[i][j]);
        }
        __syncthreads();
    }

    const float4 bv = *(const float4*)&bias[blockN + tx * 4];
    const float bre[4] = {bv.x, bv.y, bv.z, bv.w};
    #pragma unroll
    for (int i = 0; i < 4; i++) {
        float4 o;
        float v0 = acc[i][0] + bre[0];
        float v1 = acc[i][1] + bre[1];
        float v2 = acc[i][2] + bre[2];
        float v3 = acc[i][3] + bre[3];
        if (doTanh) { v0 = tanhf(v0); v1 = tanhf(v1); v2 = tanhf(v2); v3 = tanhf(v3); }
        o.x = v0; o.y = v1; o.z = v2; o.w = v3;
        *(float4*)&C[(blockM + ty * 4 + i) * N + blockN + tx * 4] = o;
    }
}

// =====================================================================
// FC2: [256,1024] @ [1024,142] + bias. One block per batch row.
// =====================================================================
__global__ void __launch_bounds__(256) fc2_kernel(const float* __restrict__ W2,
                                                  const float* __restrict__ b2)
{
    __shared__ float sh[1024];
    const int b   = blockIdx.x;
    const int tid = threadIdx.x;
    for (int i = tid; i < 1024; i += 256) sh[i] = g_h1[b * 1024 + i];
    __syncthreads();
    if (tid < 142) {
        float a0 = 0.f, a1 = 0.f, a2 = 0.f, a3 = 0.f;
        #pragma unroll 4
        for (int k = 0; k < 1024; k += 4) {
            a0 = fmaf(sh[k + 0], W2[(k + 0) * 142 + tid], a0);
            a1 = fmaf(sh[k + 1], W2[(k + 1) * 142 + tid], a1);
            a2 = fmaf(sh[k + 2], W2[(k + 2) * 142 + tid], a2);
            a3 = fmaf(sh[k + 3], W2[(k + 3) * 142 + tid], a3);
        }
        g_fc2[b * 142 + tid] = (a0 + a1) + (a2 + a3) + b2[tid];
    }
}

// =====================================================================
// DMP integration: thread per (batch, segment, dof) = 256*10*2 = 5120
// =====================================================================
__global__ void __launch_bounds__(256) dmp_kernel(float* __restrict__ out)
{
    const int g = blockIdx.x * 256 + threadIdx.x;
    if (g >= 5120) return;
    const int b = g / 20;
    const int r = g % 20;
    const int s = r >> 1;
    const int d = r & 1;

    const float* o = g_fc2 + b * 142;
    const float y0   = fminf(fmaxf(o[s * 2 + d], 0.f), 1.f);
    const float goal = fminf(fmaxf(o[(s + 1) * 2 + d], 0.f), 1.f);
    float wv[6];
    #pragma unroll
    for (int n = 0; n < 6; n++) wv[n] = o[22 + (s * 2 + d) * 6 + n];

    float cb[6], hb[6];
    #pragma unroll
    for (int n = 0; n < 6; n++) {
        cb[n] = expf(-0.2f * (float)n);            // exp(-CS_AX * linspace(0,1,6))
        hb[n] = 14.696938456699069f / cb[n];       // 6^1.5 / c / CS_AX
    }

    float xc = 1.f, y = y0, dy = 0.f;
    const float gm_y0 = goal - y0;
    float* yout = out + (b * 1000 + s * 100) * 2 + d;

    for (int t = 0; t < 100; t++) {
        xc -= xc * 0.01f;                          // canonical step
        float num = 0.f, den = 0.f;
        #pragma unroll
        for (int n = 0; n < 6; n++) {
            const float dd  = xc - cb[n];
            const float psi = expf(-hb[n] * dd * dd);
            num = fmaf(wv[n], psi, num);
            den += psi;
        }
        const float f   = xc * gm_y0 * num / den;
        const float ddy = 25.f * (6.25f * (goal - y) - dy) + f;   // AY=25, BY=6.25, TAU=1
        dy += ddy * 0.01f;
        y  += dy * 0.01f;
        yout[t * 2] = fminf(fmaxf(y, 0.f), 1.f);
    }
}

// =====================================================================
// launch
// =====================================================================
extern "C" void kernel_launch(void* const* d_in, const int* in_sizes, int n_in,
                              void* d_out, int out_size)
{
    const float* x   = (const float*)d_in[0];
    const float* c1w = (const float*)d_in[1];
    const float* c1b = (const float*)d_in[2];
    const float* c2w = (const float*)d_in[3];
    const float* c2b = (const float*)d_in[4];
    const float* W0  = (const float*)d_in[5];
    const float* b0  = (const float*)d_in[6];
    const float* W1  = (const float*)d_in[7];
    const float* b1  = (const float*)d_in[8];
    const float* W2  = (const float*)d_in[9];
    const float* b2  = (const float*)d_in[10];
    float* out = (float*)d_out;

    cudaFuncSetAttribute(conv2_kernel, cudaFuncAttributeMaxDynamicSharedMemorySize,
                         CONV2_SMEM_BYTES);

    void *p_act2 = nullptr, *p_h0 = nullptr, *p_h1 = nullptr;
    cudaGetSymbolAddress(&p_act2, g_act2);
    cudaGetSymbolAddress(&p_h0, g_h0);
    cudaGetSymbolAddress(&p_h1, g_h1);

    conv1_kernel<<<256, 256>>>(x, c1w, c1b);
    conv2_kernel<<<256, 256, CONV2_SMEM_BYTES>>>(c2w, c2b);

    // FC0: [256,9680] @ [9680,2048] + b0, tanh
    {
        dim3 grid(2048 / 64, 256 / 64);
        gemm_bias_act<<<grid, 256>>>((const float*)p_act2, W0, b0, (float*)p_h0,
                                     2048, 9680, 1);
    }
    // FC1: [256,2048] @ [2048,1024] + b1, tanh
    {
        dim3 grid(1024 / 64, 256 / 64);
        gemm_bias_act<<<grid, 256>>>((const float*)p_h0, W1, b1, (float*)p_h1,
                                     1024, 2048, 1);
    }
    fc2_kernel<<<256, 256>>>(W2, b2);
    dmp_kernel<<<20, 256>>>(out);
}

// round 5
// speedup vs baseline: 2.0990x; 2.0990x over previous
#include <cuda_runtime.h>
#include <cuda_bf16.h>
#include <math.h>
#include <stdint.h>

// ---------------- scratch (static __device__; no allocations allowed) ----------------
__device__ float g_act1[256 * 10 * 48 * 48];   // conv1 output, pooled+relu
__device__ float g_act2[256 * 20 * 22 * 22];   // conv2 output == FC0 input [256,9680]
__device__ float g_h0[256 * 2048];
__device__ float g_h1[256 * 1024];
__device__ float g_fc2[256 * 142];
__device__ float g_part[5 * 256 * 2048];       // split-K partials (max: FC0 5 slices)

// single dynamic smem symbol (conv2 only)
extern __shared__ char dyn_smem[];

// =====================================================================
// conv1 (1->10, 5x5 VALID) + bias + maxpool2 + relu, one block per image
// =====================================================================
__global__ void __launch_bounds__(256) conv1_kernel(const float* __restrict__ x,
                                                    const float* __restrict__ w,
                                                    const float* __restrict__ bias)
{
    __shared__ float sx[10000];
    __shared__ float sw[250];
    __shared__ float sb[10];
    const int b   = blockIdx.x;
    const int tid = threadIdx.x;
    const float* xin = x + b * 10000;
    for (int i = tid; i < 10000; i += 256) sx[i] = xin[i];
    if (tid < 250) sw[tid] = w[tid];
    if (tid < 10)  sb[tid] = bias[tid];
    __syncthreads();

    for (int task = tid; task < 5760; task += 256) {
        const int oc = task / 576;
        const int t  = task % 576;
        const int ti = t / 24, tj = t % 24;

        float wr[25];
        #pragma unroll
        for (int q = 0; q < 25; q++) wr[q] = sw[oc * 25 + q];

        float xr[8][8];
        #pragma unroll
        for (int r = 0; r < 8; r++)
            #pragma unroll
            for (int c = 0; c < 8; c++)
                xr[r][c] = sx[(4 * ti + r) * 100 + 4 * tj + c];

        float acc[4][4];
        #pragma unroll
        for (int r = 0; r < 4; r++)
            #pragma unroll
            for (int c = 0; c < 4; c++) acc[r][c] = 0.f;

        #pragma unroll
        for (int ki = 0; ki < 5; ki++)
            #pragma unroll
            for (int kj = 0; kj < 5; kj++) {
                const float wv = wr[ki * 5 + kj];
                #pragma unroll
                for (int r = 0; r < 4; r++)
                    #pragma unroll
                    for (int c = 0; c < 4; c++)
                        acc[r][c] = fmaf(xr[r + ki][c + kj], wv, acc[r][c]);
            }

        const float bb = sb[oc];
        float* outp = g_act1 + ((b * 10 + oc) * 48) * 48;
        #pragma unroll
        for (int pi = 0; pi < 2; pi++)
            #pragma unroll
            for (int pj = 0; pj < 2; pj++) {
                float m = fmaxf(fmaxf(acc[2*pi][2*pj],   acc[2*pi][2*pj+1]),
                                fmaxf(acc[2*pi+1][2*pj], acc[2*pi+1][2*pj+1]));
                m = fmaxf(m + bb, 0.f);
                outp[(2 * ti + pi) * 48 + 2 * tj + pj] = m;
            }
    }
}

// =====================================================================
// conv2 (10->20, 5x5 VALID) + bias + maxpool2 + relu, one block per image
// =====================================================================
#define CONV2_SMEM_BYTES ((23040 + 5000 + 32) * 4)

__global__ void __launch_bounds__(256) conv2_kernel(const float* __restrict__ w,
                                                    const float* __restrict__ bias)
{
    float* smemf = (float*)dyn_smem;
    float* sx = smemf;
    float* sw = smemf + 23040;
    float* sb = sw + 5000;
    const int b   = blockIdx.x;
    const int tid = threadIdx.x;
    const float* xin = g_act1 + b * 23040;
    for (int i = tid; i < 23040; i += 256) sx[i] = xin[i];
    for (int i = tid; i < 5000; i += 256)  sw[i] = w[i];
    if (tid < 20) sb[tid] = bias[tid];
    __syncthreads();

    for (int task = tid; task < 2420; task += 256) {
        const int oc = task / 121;
        const int t  = task % 121;
        const int ti = t / 11, tj = t % 11;

        float acc[4][4];
        #pragma unroll
        for (int r = 0; r < 4; r++)
            #pragma unroll
            for (int c = 0; c < 4; c++) acc[r][c] = 0.f;

        for (int ic = 0; ic < 10; ic++) {
            float wr[25];
            #pragma unroll
            for (int q = 0; q < 25; q++) wr[q] = sw[(oc * 10 + ic) * 25 + q];

            float xr[8][8];
            #pragma unroll
            for (int r = 0; r < 8; r++)
                #pragma unroll
                for (int c = 0; c < 8; c++)
                    xr[r][c] = sx[ic * 2304 + (4 * ti + r) * 48 + 4 * tj + c];

            #pragma unroll
            for (int ki = 0; ki < 5; ki++)
                #pragma unroll
                for (int kj = 0; kj < 5; kj++) {
                    const float wv = wr[ki * 5 + kj];
                    #pragma unroll
                    for (int r = 0; r < 4; r++)
                        #pragma unroll
                        for (int c = 0; c < 4; c++)
                            acc[r][c] = fmaf(xr[r + ki][c + kj], wv, acc[r][c]);
                }
        }

        const float bb = sb[oc];
        float* outp = g_act2 + ((b * 20 + oc) * 22) * 22;
        #pragma unroll
        for (int pi = 0; pi < 2; pi++)
            #pragma unroll
            for (int pj = 0; pj < 2; pj++) {
                float m = fmaxf(fmaxf(acc[2*pi][2*pj],   acc[2*pi][2*pj+1]),
                                fmaxf(acc[2*pi+1][2*pj], acc[2*pi+1][2*pj+1]));
                m = fmaxf(m + bb, 0.f);
                outp[(2 * ti + pi) * 22 + 2 * tj + pj] = m;
            }
    }
}

// =====================================================================
// mma.sync bf16-split GEMM with split-K.
// C_partial[s][M,N] = A[M, kslice] @ B[kslice, N]
// CTA tile 128x128, 256 thr (8 warps, each 64x32), k-chunk 32.
// A smem: [m][k] bf16 stride 40 (hi,lo); B smem: [n][k] bf16 stride 40 (hi,lo).
// 3 passes: Ah*Bh + Ah*Bl + Al*Bh, fp32 accum.
// =====================================================================
__device__ __forceinline__ void mma16816(float c[4], const uint32_t a[4], const uint32_t b[2]) {
    asm volatile(
        "mma.sync.aligned.m16n8k16.row.col.f32.bf16.bf16.f32 "
        "{%0,%1,%2,%3}, {%4,%5,%6,%7}, {%8,%9}, {%0,%1,%2,%3};"
        : "+f"(c[0]), "+f"(c[1]), "+f"(c[2]), "+f"(c[3])
        : "r"(a[0]), "r"(a[1]), "r"(a[2]), "r"(a[3]), "r"(b[0]), "r"(b[1]));
}

__global__ void __launch_bounds__(256) gemm_mma(const float* __restrict__ A,
                                                const float* __restrict__ B,
                                                float* __restrict__ part,
                                                int N, int K, int kLen)
{
    __shared__ __nv_bfloat16 Ah[128 * 40];
    __shared__ __nv_bfloat16 Al[128 * 40];
    __shared__ __nv_bfloat16 Bh[128 * 40];
    __shared__ __nv_bfloat16 Bl[128 * 40];

    const int tid  = threadIdx.x;
    const int wid  = tid >> 5;
    const int lane = tid & 31;
    const int g    = lane >> 2;     // group 0..7
    const int t    = lane & 3;      // 0..3
    const int warpM = wid >> 2;     // 0..1 -> m offset *64
    const int warpN = wid & 3;      // 0..3 -> n offset *32

    const int nBase = blockIdx.x * 128;
    const int mBase = blockIdx.y * 128;
    const int s     = blockIdx.z;
    const int kBeg  = s * kLen;
    const int kEnd  = (kBeg + kLen < K) ? (kBeg + kLen) : K;

    float acc[4][4][4];
    #pragma unroll
    for (int i = 0; i < 4; i++)
        #pragma unroll
        for (int j = 0; j < 4; j++)
            #pragma unroll
            for (int q = 0; q < 4; q++) acc[i][j][q] = 0.f;

    const uint32_t* Ah32 = (const uint32_t*)Ah;
    const uint32_t* Al32 = (const uint32_t*)Al;
    const uint32_t* Bh32 = (const uint32_t*)Bh;
    const uint32_t* Bl32 = (const uint32_t*)Bl;

    // B staging indices: thread -> (khalf, n)
    const int bHalf = tid >> 7;        // 0/1 -> k sub-block of 16
    const int bN    = tid & 127;       // n within tile

    for (int kc = kBeg; kc < kEnd; kc += 32) {
        // ---- A tile: 128 rows x 32 k, pair-per-thread iterations ----
        #pragma unroll
        for (int i = 0; i < 8; i++) {
            const int idx2 = (tid + 256 * i) * 2;
            const int row = idx2 >> 5;
            const int k   = idx2 & 31;
            const int gk  = kc + k;
            const float v0 = (gk     < kEnd) ? A[(mBase + row) * K + gk]     : 0.f;
            const float v1 = (gk + 1 < kEnd) ? A[(mBase + row) * K + gk + 1] : 0.f;
            const __nv_bfloat16 h0 = __float2bfloat16(v0);
            const __nv_bfloat16 h1 = __float2bfloat16(v1);
            const __nv_bfloat16 l0 = __float2bfloat16(v0 - __bfloat162float(h0));
            const __nv_bfloat16 l1 = __float2bfloat16(v1 - __bfloat162float(h1));
            *(__nv_bfloat162*)&Ah[row * 40 + k] = __halves2bfloat162(h0, h1);
            *(__nv_bfloat162*)&Al[row * 40 + k] = __halves2bfloat162(l0, l1);
        }
        // ---- B tile: 32 k x 128 n, register-staged transpose to [n][k] ----
        {
            float vb[16];
            #pragma unroll
            for (int kk = 0; kk < 16; kk++) {
                const int gk = kc + bHalf * 16 + kk;
                vb[kk] = (gk < kEnd) ? B[(size_t)gk * N + nBase + bN] : 0.f;
            }
            #pragma unroll
            for (int kk = 0; kk < 8; kk++) {
                const float v0 = vb[2 * kk], v1 = vb[2 * kk + 1];
                const __nv_bfloat16 h0 = __float2bfloat16(v0);
                const __nv_bfloat16 h1 = __float2bfloat16(v1);
                const __nv_bfloat16 l0 = __float2bfloat16(v0 - __bfloat162float(h0));
                const __nv_bfloat16 l1 = __float2bfloat16(v1 - __bfloat162float(h1));
                const int off = bN * 40 + bHalf * 16 + 2 * kk;
                *(__nv_bfloat162*)&Bh[off] = __halves2bfloat162(h0, h1);
                *(__nv_bfloat162*)&Bl[off] = __halves2bfloat162(l0, l1);
            }
        }
        __syncthreads();

        #pragma unroll
        for (int ks = 0; ks < 2; ks++) {
            const int kw = ks * 8;     // k offset in 32-bit words (16 bf16)
            uint32_t ah[4][4], al[4][4], bh[4][2], bl[4][2];
            #pragma unroll
            for (int mt = 0; mt < 4; mt++) {
                const int r0 = (warpM * 64 + mt * 16 + g) * 20;
                const int r8 = r0 + 8 * 20;
                ah[mt][0] = Ah32[r0 + kw + t];
                ah[mt][1] = Ah32[r8 + kw + t];
                ah[mt][2] = Ah32[r0 + kw + t + 4];
                ah[mt][3] = Ah32[r8 + kw + t + 4];
                al[mt][0] = Al32[r0 + kw + t];
                al[mt][1] = Al32[r8 + kw + t];
                al[mt][2] = Al32[r0 + kw + t + 4];
                al[mt][3] = Al32[r8 + kw + t + 4];
            }
            #pragma unroll
            for (int nt = 0; nt < 4; nt++) {
                const int n0 = (warpN * 32 + nt * 8 + g) * 20;
                bh[nt][0] = Bh32[n0 + kw + t];
                bh[nt][1] = Bh32[n0 + kw + t + 4];
                bl[nt][0] = Bl32[n0 + kw + t];
                bl[nt][1] = Bl32[n0 + kw + t + 4];
            }
            #pragma unroll
            for (int mt = 0; mt < 4; mt++)
                #pragma unroll
                for (int nt = 0; nt < 4; nt++) {
                    mma16816(acc[mt][nt], ah[mt], bh[nt]);
                    mma16816(acc[mt][nt], ah[mt], bl[nt]);
                    mma16816(acc[mt][nt], al[mt], bh[nt]);
                }
        }
        __syncthreads();
    }

    // ---- epilogue: write partials ----
    float* P = part + (size_t)s * 256 * N;
    #pragma unroll
    for (int mt = 0; mt < 4; mt++) {
        const int m = mBase + warpM * 64 + mt * 16 + g;
        #pragma unroll
        for (int nt = 0; nt < 4; nt++) {
            const int n = nBase + warpN * 32 + nt * 8 + t * 2;
            float2 v0; v0.x = acc[mt][nt][0]; v0.y = acc[mt][nt][1];
            float2 v1; v1.x = acc[mt][nt][2]; v1.y = acc[mt][nt][3];
            *(float2*)&P[(size_t)m * N + n]       = v0;
            *(float2*)&P[(size_t)(m + 8) * N + n] = v1;
        }
    }
}

// =====================================================================
// reduce split-K partials + bias + optional tanh
// =====================================================================
__global__ void __launch_bounds__(256) reduce_act(const float* __restrict__ part,
                                                  const float* __restrict__ bias,
                                                  float* __restrict__ C,
                                                  int N, int S, int doTanh)
{
    const size_t idx = (size_t)blockIdx.x * 256 + threadIdx.x;
    const size_t MN = (size_t)256 * N;
    float v = bias[idx % N];
    for (int s = 0; s < S; s++) v += part[s * MN + idx];
    if (doTanh) v = tanhf(v);
    C[idx] = v;
}

// =====================================================================
// FC2: [256,1024] @ [1024,142] + bias. One block per batch row.
// =====================================================================
__global__ void __launch_bounds__(256) fc2_kernel(const float* __restrict__ W2,
                                                  const float* __restrict__ b2)
{
    __shared__ float sh[1024];
    const int b   = blockIdx.x;
    const int tid = threadIdx.x;
    for (int i = tid; i < 1024; i += 256) sh[i] = g_h1[b * 1024 + i];
    __syncthreads();
    if (tid < 142) {
        float a0 = 0.f, a1 = 0.f, a2 = 0.f, a3 = 0.f;
        #pragma unroll 4
        for (int k = 0; k < 1024; k += 4) {
            a0 = fmaf(sh[k + 0], W2[(k + 0) * 142 + tid], a0);
            a1 = fmaf(sh[k + 1], W2[(k + 1) * 142 + tid], a1);
            a2 = fmaf(sh[k + 2], W2[(k + 2) * 142 + tid], a2);
            a3 = fmaf(sh[k + 3], W2[(k + 3) * 142 + tid], a3);
        }
        g_fc2[b * 142 + tid] = (a0 + a1) + (a2 + a3) + b2[tid];
    }
}

// =====================================================================
// DMP integration: thread per (batch, segment, dof) = 5120
// =====================================================================
__global__ void __launch_bounds__(256) dmp_kernel(float* __restrict__ out)
{
    const int gidx = blockIdx.x * 256 + threadIdx.x;
    if (gidx >= 5120) return;
    const int b = gidx / 20;
    const int r = gidx % 20;
    const int s = r >> 1;
    const int d = r & 1;

    const float* o = g_fc2 + b * 142;
    const float y0   = fminf(fmaxf(o[s * 2 + d], 0.f), 1.f);
    const float goal = fminf(fmaxf(o[(s + 1) * 2 + d], 0.f), 1.f);
    float wv[6];
    #pragma unroll
    for (int n = 0; n < 6; n++) wv[n] = o[22 + (s * 2 + d) * 6 + n];

    float cb[6], hb[6];
    #pragma unroll
    for (int n = 0; n < 6; n++) {
        cb[n] = expf(-0.2f * (float)n);
        hb[n] = 14.696938456699069f / cb[n];
    }

    float xc = 1.f, y = y0, dy = 0.f;
    const float gm_y0 = goal - y0;
    float* yout = out + (b * 1000 + s * 100) * 2 + d;

    for (int t = 0; t < 100; t++) {
        xc -= xc * 0.01f;
        float num = 0.f, den = 0.f;
        #pragma unroll
        for (int n = 0; n < 6; n++) {
            const float dd  = xc - cb[n];
            const float psi = expf(-hb[n] * dd * dd);
            num = fmaf(wv[n], psi, num);
            den += psi;
        }
        const float f   = xc * gm_y0 * num / den;
        const float ddy = 25.f * (6.25f * (goal - y) - dy) + f;
        dy += ddy * 0.01f;
        y  += dy * 0.01f;
        yout[t * 2] = fminf(fmaxf(y, 0.f), 1.f);
    }
}

// =====================================================================
// launch
// =====================================================================
extern "C" void kernel_launch(void* const* d_in, const int* in_sizes, int n_in,
                              void* d_out, int out_size)
{
    const float* x   = (const float*)d_in[0];
    const float* c1w = (const float*)d_in[1];
    const float* c1b = (const float*)d_in[2];
    const float* c2w = (const float*)d_in[3];
    const float* c2b = (const float*)d_in[4];
    const float* W0  = (const float*)d_in[5];
    const float* b0  = (const float*)d_in[6];
    const float* W1  = (const float*)d_in[7];
    const float* b1  = (const float*)d_in[8];
    const float* W2  = (const float*)d_in[9];
    const float* b2  = (const float*)d_in[10];
    float* out = (float*)d_out;

    cudaFuncSetAttribute(conv2_kernel, cudaFuncAttributeMaxDynamicSharedMemorySize,
                         CONV2_SMEM_BYTES);

    void *p_act2 = nullptr, *p_h0 = nullptr, *p_h1 = nullptr, *p_part = nullptr;
    cudaGetSymbolAddress(&p_act2, g_act2);
    cudaGetSymbolAddress(&p_h0, g_h0);
    cudaGetSymbolAddress(&p_h1, g_h1);
    cudaGetSymbolAddress(&p_part, g_part);

    conv1_kernel<<<256, 256>>>(x, c1w, c1b);
    conv2_kernel<<<256, 256, CONV2_SMEM_BYTES>>>(c2w, c2b);

    // FC0: [256,9680] @ [9680,2048], split-K=5 (slices of 1936)
    {
        dim3 grid(2048 / 128, 256 / 128, 5);
        gemm_mma<<<grid, 256>>>((const float*)p_act2, W0, (float*)p_part,
                                2048, 9680, 1936);
        reduce_act<<<(256 * 2048) / 256, 256>>>((const float*)p_part, b0,
                                                (float*)p_h0, 2048, 5, 1);
    }
    // FC1: [256,2048] @ [2048,1024], split-K=8 (slices of 256)
    {
        dim3 grid(1024 / 128, 256 / 128, 8);
        gemm_mma<<<grid, 256>>>((const float*)p_h0, W1, (float*)p_part,
                                1024, 2048, 256);
        reduce_act<<<(256 * 1024) / 256, 256>>>((const float*)p_part, b1,
                                                (float*)p_h1, 1024, 8, 1);
    }
    fc2_kernel<<<256, 256>>>(W2, b2);
    dmp_kernel<<<20, 256>>>(out);
}

// round 6
// speedup vs baseline: 2.5517x; 1.2157x over previous
#include <cuda_runtime.h>
#include <cuda_bf16.h>
#include <math.h>
#include <stdint.h>

// ---------------- scratch (static __device__; no allocations allowed) ----------------
#define KPAD 9696   // 9680 padded to multiple of 32

__device__ float g_act1[256 * 10 * 48 * 48];       // conv1 output, pooled+relu
__device__ __nv_bfloat16 g_act2h[256 * KPAD];      // conv2 out hi (FC0 A)
__device__ __nv_bfloat16 g_act2l[256 * KPAD];      // conv2 out lo
__device__ __nv_bfloat16 g_W0h[KPAD * 2048];
__device__ __nv_bfloat16 g_W0l[KPAD * 2048];
__device__ __nv_bfloat16 g_W1h[2048 * 1024];
__device__ __nv_bfloat16 g_W1l[2048 * 1024];
__device__ __nv_bfloat16 g_h0h[256 * 2048];        // FC0 out hi (FC1 A)
__device__ __nv_bfloat16 g_h0l[256 * 2048];
__device__ float g_h1[256 * 1024];
__device__ float g_fc2[256 * 142];
__device__ float g_part[5 * 256 * 2048];           // split-K partials

extern __shared__ char dyn_smem[];

// ---------------- helpers ----------------
__device__ __forceinline__ uint32_t smem_u32(const void* p) {
    uint32_t a;
    asm("{ .reg .u64 t; cvta.to.shared.u64 t, %1; cvt.u32.u64 %0, t; }" : "=r"(a) : "l"(p));
    return a;
}
__device__ __forceinline__ void cp16(uint32_t dst, const void* src) {
    asm volatile("cp.async.cg.shared.global [%0], [%1], 16;" :: "r"(dst), "l"(src));
}
__device__ __forceinline__ void cp_commit() {
    asm volatile("cp.async.commit_group;" ::: "memory");
}
__device__ __forceinline__ void ldsm_x4(uint32_t r[4], uint32_t addr) {
    asm volatile("ldmatrix.sync.aligned.m8n8.x4.shared.b16 {%0,%1,%2,%3}, [%4];"
                 : "=r"(r[0]), "=r"(r[1]), "=r"(r[2]), "=r"(r[3]) : "r"(addr));
}
__device__ __forceinline__ void ldsm_x2t(uint32_t r[2], uint32_t addr) {
    asm volatile("ldmatrix.sync.aligned.m8n8.x2.trans.shared.b16 {%0,%1}, [%2];"
                 : "=r"(r[0]), "=r"(r[1]) : "r"(addr));
}
__device__ __forceinline__ void mma16816(float c[4], const uint32_t a[4], const uint32_t b[2]) {
    asm volatile(
        "mma.sync.aligned.m16n8k16.row.col.f32.bf16.bf16.f32 "
        "{%0,%1,%2,%3}, {%4,%5,%6,%7}, {%8,%9}, {%0,%1,%2,%3};"
        : "+f"(c[0]), "+f"(c[1]), "+f"(c[2]), "+f"(c[3])
        : "r"(a[0]), "r"(a[1]), "r"(a[2]), "r"(a[3]), "r"(b[0]), "r"(b[1]));
}
__device__ __forceinline__ void split_bf16(float v, __nv_bfloat16& h, __nv_bfloat16& l) {
    h = __float2bfloat16(v);
    l = __float2bfloat16(v - __bfloat162float(h));
}

// =====================================================================
// conv1 (1->10, 5x5 VALID) + bias + maxpool2 + relu, one block per image
// =====================================================================
__global__ void __launch_bounds__(256) conv1_kernel(const float* __restrict__ x,
                                                    const float* __restrict__ w,
                                                    const float* __restrict__ bias)
{
    __shared__ float sx[10000];
    __shared__ float sw[250];
    __shared__ float sb[10];
    const int b   = blockIdx.x;
    const int tid = threadIdx.x;
    const float* xin = x + b * 10000;
    for (int i = tid; i < 10000; i += 256) sx[i] = xin[i];
    if (tid < 250) sw[tid] = w[tid];
    if (tid < 10)  sb[tid] = bias[tid];
    __syncthreads();

    for (int task = tid; task < 5760; task += 256) {
        const int oc = task / 576;
        const int t  = task % 576;
        const int ti = t / 24, tj = t % 24;

        float wr[25];
        #pragma unroll
        for (int q = 0; q < 25; q++) wr[q] = sw[oc * 25 + q];

        float xr[8][8];
        #pragma unroll
        for (int r = 0; r < 8; r++)
            #pragma unroll
            for (int c = 0; c < 8; c++)
                xr[r][c] = sx[(4 * ti + r) * 100 + 4 * tj + c];

        float acc[4][4];
        #pragma unroll
        for (int r = 0; r < 4; r++)
            #pragma unroll
            for (int c = 0; c < 4; c++) acc[r][c] = 0.f;

        #pragma unroll
        for (int ki = 0; ki < 5; ki++)
            #pragma unroll
            for (int kj = 0; kj < 5; kj++) {
                const float wv = wr[ki * 5 + kj];
                #pragma unroll
                for (int r = 0; r < 4; r++)
                    #pragma unroll
                    for (int c = 0; c < 4; c++)
                        acc[r][c] = fmaf(xr[r + ki][c + kj], wv, acc[r][c]);
            }

        const float bb = sb[oc];
        float* outp = g_act1 + ((b * 10 + oc) * 48) * 48;
        #pragma unroll
        for (int pi = 0; pi < 2; pi++)
            #pragma unroll
            for (int pj = 0; pj < 2; pj++) {
                float m = fmaxf(fmaxf(acc[2*pi][2*pj],   acc[2*pi][2*pj+1]),
                                fmaxf(acc[2*pi+1][2*pj], acc[2*pi+1][2*pj+1]));
                m = fmaxf(m + bb, 0.f);
                outp[(2 * ti + pi) * 48 + 2 * tj + pj] = m;
            }
    }
}

// =====================================================================
// conv2 (10->20, 5x5 VALID) + bias + maxpool2 + relu -> bf16 hi/lo act2
// =====================================================================
#define CONV2_SMEM_BYTES ((23040 + 5000 + 32) * 4)

__global__ void __launch_bounds__(256) conv2_kernel(const float* __restrict__ w,
                                                    const float* __restrict__ bias)
{
    float* smemf = (float*)dyn_smem;
    float* sx = smemf;
    float* sw = smemf + 23040;
    float* sb = sw + 5000;
    const int b   = blockIdx.x;
    const int tid = threadIdx.x;
    const float* xin = g_act1 + b * 23040;
    for (int i = tid; i < 23040; i += 256) sx[i] = xin[i];
    for (int i = tid; i < 5000; i += 256)  sw[i] = w[i];
    if (tid < 20) sb[tid] = bias[tid];
    __syncthreads();

    for (int task = tid; task < 2420; task += 256) {
        const int oc = task / 121;
        const int t  = task % 121;
        const int ti = t / 11, tj = t % 11;

        float acc[4][4];
        #pragma unroll
        for (int r = 0; r < 4; r++)
            #pragma unroll
            for (int c = 0; c < 4; c++) acc[r][c] = 0.f;

        for (int ic = 0; ic < 10; ic++) {
            float wr[25];
            #pragma unroll
            for (int q = 0; q < 25; q++) wr[q] = sw[(oc * 10 + ic) * 25 + q];

            float xr[8][8];
            #pragma unroll
            for (int r = 0; r < 8; r++)
                #pragma unroll
                for (int c = 0; c < 8; c++)
                    xr[r][c] = sx[ic * 2304 + (4 * ti + r) * 48 + 4 * tj + c];

            #pragma unroll
            for (int ki = 0; ki < 5; ki++)
                #pragma unroll
                for (int kj = 0; kj < 5; kj++) {
                    const float wv = wr[ki * 5 + kj];
                    #pragma unroll
                    for (int r = 0; r < 4; r++)
                        #pragma unroll
                        for (int c = 0; c < 4; c++)
                            acc[r][c] = fmaf(xr[r + ki][c + kj], wv, acc[r][c]);
                }
        }

        const float bb = sb[oc];
        #pragma unroll
        for (int pi = 0; pi < 2; pi++)
            #pragma unroll
            for (int pj = 0; pj < 2; pj++) {
                float m = fmaxf(fmaxf(acc[2*pi][2*pj],   acc[2*pi][2*pj+1]),
                                fmaxf(acc[2*pi+1][2*pj], acc[2*pi+1][2*pj+1]));
                m = fmaxf(m + bb, 0.f);
                const int col = oc * 484 + (2 * ti + pi) * 22 + 2 * tj + pj;
                __nv_bfloat16 h, l;
                split_bf16(m, h, l);
                g_act2h[b * KPAD + col] = h;
                g_act2l[b * KPAD + col] = l;
            }
    }
}

// zero the pad columns [9680, 9696) of act2 hi/lo
__global__ void pad_act2_kernel() {
    const int i = blockIdx.x * 256 + threadIdx.x;
    if (i < 256 * 16) {
        const int b = i >> 4, c = 9680 + (i & 15);
        g_act2h[b * KPAD + c] = __float2bfloat16(0.f);
        g_act2l[b * KPAD + c] = __float2bfloat16(0.f);
    }
}

// =====================================================================
// weight split: fp32 W -> bf16 hi/lo (pad region zeroed), vectorized x4
// =====================================================================
__global__ void __launch_bounds__(256) wsplit_kernel(const float* __restrict__ W,
                                                     __nv_bfloat16* __restrict__ Wh,
                                                     __nv_bfloat16* __restrict__ Wl,
                                                     int valid4, int total4)
{
    for (int i = blockIdx.x * 256 + threadIdx.x; i < total4; i += gridDim.x * 256) {
        float4 w = (i < valid4) ? ((const float4*)W)[i] : make_float4(0.f, 0.f, 0.f, 0.f);
        __nv_bfloat16 h0, h1, h2, h3, l0, l1, l2, l3;
        split_bf16(w.x, h0, l0); split_bf16(w.y, h1, l1);
        split_bf16(w.z, h2, l2); split_bf16(w.w, h3, l3);
        __nv_bfloat162 ha = __halves2bfloat162(h0, h1), hb = __halves2bfloat162(h2, h3);
        __nv_bfloat162 la = __halves2bfloat162(l0, l1), lb = __halves2bfloat162(l2, l3);
        uint2 uh, ul;
        uh.x = *(uint32_t*)&ha; uh.y = *(uint32_t*)&hb;
        ul.x = *(uint32_t*)&la; ul.y = *(uint32_t*)&lb;
        ((uint2*)Wh)[i] = uh;
        ((uint2*)Wl)[i] = ul;
    }
}

// =====================================================================
// bf16 split-K GEMM: cp.async double-buffered, ldmatrix fragments.
// CTA tile 128x128, 256 thr (8 warps each 64x32), k-chunk 32.
// A smem [m][k] stride 40 bf16; B smem [k][n] stride 136 bf16.
// 3 passes Ah*Bh + Ah*Bl + Al*Bh accumulated fp32.
// =====================================================================
#define GA_H 0
#define GA_L 10240
#define GB_H 20480
#define GB_L 29184
#define GBUF 37888
#define GEMM_SMEM_BYTES (2 * GBUF)

__global__ void __launch_bounds__(256) gemm_bf16(const __nv_bfloat16* __restrict__ Ah_g,
                                                 const __nv_bfloat16* __restrict__ Al_g,
                                                 const __nv_bfloat16* __restrict__ Bh_g,
                                                 const __nv_bfloat16* __restrict__ Bl_g,
                                                 float* __restrict__ part,
                                                 int N, int strideA, int Ktot, int kLen)
{
    const uint32_t sb = smem_u32(dyn_smem);
    const int tid  = threadIdx.x;
    const int wid  = tid >> 5;
    const int lane = tid & 31;
    const int g    = lane >> 2;
    const int t    = lane & 3;
    const int warpM = wid >> 2;     // 0..1
    const int warpN = wid & 3;      // 0..3

    const int nBase = blockIdx.x * 128;
    const int mBase = blockIdx.y * 128;
    const int s     = blockIdx.z;
    const int kBeg  = s * kLen;
    const int kEnd  = (kBeg + kLen < Ktot) ? (kBeg + kLen) : Ktot;
    const int nCh   = (kEnd - kBeg) >> 5;

    float acc[4][4][4];
    #pragma unroll
    for (int i = 0; i < 4; i++)
        #pragma unroll
        for (int j = 0; j < 4; j++)
            #pragma unroll
            for (int q = 0; q < 4; q++) acc[i][j][q] = 0.f;

    // staging indices
    const int aRow = tid >> 1;                 // 0..127  (2 chunks/row... see below)
    // A tile: 128 rows x 64B = 512 x 16B chunks; 2 per thread
    // B tile: 32 rows x 256B = 512 x 16B chunks; 2 per thread

    auto issue = [&](int buf, int k0) {
        const uint32_t base = sb + buf * GBUF;
        #pragma unroll
        for (int i = 0; i < 2; i++) {
            const int idx = tid + 256 * i;      // 0..511
            const int row = idx >> 2;
            const int off = idx & 3;
            const size_t so = (size_t)(mBase + row) * strideA + k0 + off * 8;
            cp16(base + GA_H + row * 80 + off * 16, Ah_g + so);
            cp16(base + GA_L + row * 80 + off * 16, Al_g + so);
        }
        #pragma unroll
        for (int i = 0; i < 2; i++) {
            const int idx = tid + 256 * i;
            const int kr  = idx >> 4;
            const int off = idx & 15;
            const size_t so = (size_t)(k0 + kr) * N + nBase + off * 8;
            cp16(base + GB_H + kr * 272 + off * 16, Bh_g + so);
            cp16(base + GB_L + kr * 272 + off * 16, Bl_g + so);
        }
    };

    issue(0, kBeg);
    cp_commit();

    for (int c = 0; c < nCh; c++) {
        if (c + 1 < nCh) {
            issue((c + 1) & 1, kBeg + (c + 1) * 32);
            cp_commit();
            asm volatile("cp.async.wait_group 1;" ::: "memory");
        } else {
            asm volatile("cp.async.wait_group 0;" ::: "memory");
        }
        __syncthreads();

        const uint32_t base = sb + (c & 1) * GBUF;
        #pragma unroll
        for (int ks = 0; ks < 2; ks++) {
            uint32_t ah[4][4], al[4][4], bh[4][2], bl[4][2];
            const uint32_t aCol = (ks * 16 + ((lane >> 4) << 3)) * 2;
            const uint32_t aR   = warpM * 64 + (lane & 15);
            #pragma unroll
            for (int mt = 0; mt < 4; mt++) {
                const uint32_t ad = base + GA_H + (aR + mt * 16) * 80 + aCol;
                ldsm_x4(ah[mt], ad);
                ldsm_x4(al[mt], ad + (GA_L - GA_H));
            }
            const uint32_t bR = ks * 16 + (lane & 15);
            #pragma unroll
            for (int nt = 0; nt < 4; nt++) {
                const uint32_t bd = base + GB_H + bR * 272 + (warpN * 32 + nt * 8) * 2;
                ldsm_x2t(bh[nt], bd);
                ldsm_x2t(bl[nt], bd + (GB_L - GB_H));
            }
            #pragma unroll
            for (int mt = 0; mt < 4; mt++)
                #pragma unroll
                for (int nt = 0; nt < 4; nt++) {
                    mma16816(acc[mt][nt], ah[mt], bh[nt]);
                    mma16816(acc[mt][nt], ah[mt], bl[nt]);
                    mma16816(acc[mt][nt], al[mt], bh[nt]);
                }
        }
        __syncthreads();
    }

    // epilogue: write partials
    float* P = part + (size_t)s * 256 * N;
    #pragma unroll
    for (int mt = 0; mt < 4; mt++) {
        const int m = mBase + warpM * 64 + mt * 16 + g;
        #pragma unroll
        for (int nt = 0; nt < 4; nt++) {
            const int n = nBase + warpN * 32 + nt * 8 + t * 2;
            float2 v0; v0.x = acc[mt][nt][0]; v0.y = acc[mt][nt][1];
            float2 v1; v1.x = acc[mt][nt][2]; v1.y = acc[mt][nt][3];
            *(float2*)&P[(size_t)m * N + n]       = v0;
            *(float2*)&P[(size_t)(m + 8) * N + n] = v1;
        }
    }
}

// =====================================================================
// reduce split-K partials + bias + tanh -> bf16 hi/lo (FC0 output)
// =====================================================================
__global__ void __launch_bounds__(256) reduce_bf16(const float* __restrict__ part,
                                                   const float* __restrict__ bias,
                                                   __nv_bfloat16* __restrict__ Ch,
                                                   __nv_bfloat16* __restrict__ Cl,
                                                   int N, int S)
{
    const size_t idx = (size_t)blockIdx.x * 256 + threadIdx.x;
    const size_t MN = (size_t)256 * N;
    float v = bias[idx % N];
    for (int s = 0; s < S; s++) v += part[s * MN + idx];
    v = tanhf(v);
    __nv_bfloat16 h, l;
    split_bf16(v, h, l);
    Ch[idx] = h;
    Cl[idx] = l;
}

// reduce split-K partials + bias + tanh -> fp32 (FC1 output)
__global__ void __launch_bounds__(256) reduce_f32(const float* __restrict__ part,
                                                  const float* __restrict__ bias,
                                                  float* __restrict__ C,
                                                  int N, int S)
{
    const size_t idx = (size_t)blockIdx.x * 256 + threadIdx.x;
    const size_t MN = (size_t)256 * N;
    float v = bias[idx % N];
    for (int s = 0; s < S; s++) v += part[s * MN + idx];
    C[idx] = tanhf(v);
}

// =====================================================================
// FC2: [256,1024] @ [1024,142] + bias. One block per batch row.
// =====================================================================
__global__ void __launch_bounds__(256) fc2_kernel(const float* __restrict__ W2,
                                                  const float* __restrict__ b2)
{
    __shared__ float sh[1024];
    const int b   = blockIdx.x;
    const int tid = threadIdx.x;
    for (int i = tid; i < 1024; i += 256) sh[i] = g_h1[b * 1024 + i];
    __syncthreads();
    if (tid < 142) {
        float a0 = 0.f, a1 = 0.f, a2 = 0.f, a3 = 0.f;
        #pragma unroll 4
        for (int k = 0; k < 1024; k += 4) {
            a0 = fmaf(sh[k + 0], W2[(k + 0) * 142 + tid], a0);
            a1 = fmaf(sh[k + 1], W2[(k + 1) * 142 + tid], a1);
            a2 = fmaf(sh[k + 2], W2[(k + 2) * 142 + tid], a2);
            a3 = fmaf(sh[k + 3], W2[(k + 3) * 142 + tid], a3);
        }
        g_fc2[b * 142 + tid] = (a0 + a1) + (a2 + a3) + b2[tid];
    }
}

// =====================================================================
// DMP integration: thread per (batch, segment, dof) = 5120
// =====================================================================
__global__ void __launch_bounds__(256) dmp_kernel(float* __restrict__ out)
{
    const int gidx = blockIdx.x * 256 + threadIdx.x;
    if (gidx >= 5120) return;
    const int b = gidx / 20;
    const int r = gidx % 20;
    const int s = r >> 1;
    const int d = r & 1;

    const float* o = g_fc2 + b * 142;
    const float y0   = fminf(fmaxf(o[s * 2 + d], 0.f), 1.f);
    const float goal = fminf(fmaxf(o[(s + 1) * 2 + d], 0.f), 1.f);
    float wv[6];
    #pragma unroll
    for (int n = 0; n < 6; n++) wv[n] = o[22 + (s * 2 + d) * 6 + n];

    float cb[6], hb[6];
    #pragma unroll
    for (int n = 0; n < 6; n++) {
        cb[n] = expf(-0.2f * (float)n);
        hb[n] = 14.696938456699069f / cb[n];
    }

    float xc = 1.f, y = y0, dy = 0.f;
    const float gm_y0 = goal - y0;
    float* yout = out + (b * 1000 + s * 100) * 2 + d;

    for (int t = 0; t < 100; t++) {
        xc -= xc * 0.01f;
        float num = 0.f, den = 0.f;
        #pragma unroll
        for (int n = 0; n < 6; n++) {
            const float dd  = xc - cb[n];
            const float psi = expf(-hb[n] * dd * dd);
            num = fmaf(wv[n], psi, num);
            den += psi;
        }
        const float f   = xc * gm_y0 * num / den;
        const float ddy = 25.f * (6.25f * (goal - y) - dy) + f;
        dy += ddy * 0.01f;
        y  += dy * 0.01f;
        yout[t * 2] = fminf(fmaxf(y, 0.f), 1.f);
    }
}

// =====================================================================
// launch
// =====================================================================
extern "C" void kernel_launch(void* const* d_in, const int* in_sizes, int n_in,
                              void* d_out, int out_size)
{
    const float* x   = (const float*)d_in[0];
    const float* c1w = (const float*)d_in[1];
    const float* c1b = (const float*)d_in[2];
    const float* c2w = (const float*)d_in[3];
    const float* c2b = (const float*)d_in[4];
    const float* W0  = (const float*)d_in[5];
    const float* b0  = (const float*)d_in[6];
    const float* W1  = (const float*)d_in[7];
    const float* b1  = (const float*)d_in[8];
    const float* W2  = (const float*)d_in[9];
    const float* b2  = (const float*)d_in[10];
    float* out = (float*)d_out;

    cudaFuncSetAttribute(conv2_kernel, cudaFuncAttributeMaxDynamicSharedMemorySize,
                         CONV2_SMEM_BYTES);
    cudaFuncSetAttribute(gemm_bf16, cudaFuncAttributeMaxDynamicSharedMemorySize,
                         GEMM_SMEM_BYTES);

    void *p_a2h, *p_a2l, *p_w0h, *p_w0l, *p_w1h, *p_w1l, *p_h0h, *p_h0l, *p_part;
    cudaGetSymbolAddress(&p_a2h, g_act2h);
    cudaGetSymbolAddress(&p_a2l, g_act2l);
    cudaGetSymbolAddress(&p_w0h, g_W0h);
    cudaGetSymbolAddress(&p_w0l, g_W0l);
    cudaGetSymbolAddress(&p_w1h, g_W1h);
    cudaGetSymbolAddress(&p_w1l, g_W1l);
    cudaGetSymbolAddress(&p_h0h, g_h0h);
    cudaGetSymbolAddress(&p_h0l, g_h0l);
    cudaGetSymbolAddress(&p_part, g_part);
    void* p_h1; cudaGetSymbolAddress(&p_h1, g_h1);

    // weight preprocessing (also covers zero padding of W0 rows 9680..9695)
    wsplit_kernel<<<2048, 256>>>(W0, (__nv_bfloat16*)p_w0h, (__nv_bfloat16*)p_w0l,
                                 (9680 * 2048) / 4, (KPAD * 2048) / 4);
    wsplit_kernel<<<1024, 256>>>(W1, (__nv_bfloat16*)p_w1h, (__nv_bfloat16*)p_w1l,
                                 (2048 * 1024) / 4, (2048 * 1024) / 4);

    conv1_kernel<<<256, 256>>>(x, c1w, c1b);
    conv2_kernel<<<256, 256, CONV2_SMEM_BYTES>>>(c2w, c2b);
    pad_act2_kernel<<<16, 256>>>();

    // FC0: [256,9696p] @ [9696p,2048], split-K=4 (slices 2432; last 2400)
    {
        dim3 grid(2048 / 128, 256 / 128, 4);
        gemm_bf16<<<grid, 256, GEMM_SMEM_BYTES>>>(
            (const __nv_bfloat16*)p_a2h, (const __nv_bfloat16*)p_a2l,
            (const __nv_bfloat16*)p_w0h, (const __nv_bfloat16*)p_w0l,
            (float*)p_part, 2048, KPAD, KPAD, 2432);
        reduce_bf16<<<(256 * 2048) / 256, 256>>>((const float*)p_part, b0,
                                                 (__nv_bfloat16*)p_h0h,
                                                 (__nv_bfloat16*)p_h0l, 2048, 4);
    }
    // FC1: [256,2048] @ [2048,1024], split-K=8 (slices 256)
    {
        dim3 grid(1024 / 128, 256 / 128, 8);
        gemm_bf16<<<grid, 256, GEMM_SMEM_BYTES>>>(
            (const __nv_bfloat16*)p_h0h, (const __nv_bfloat16*)p_h0l,
            (const __nv_bfloat16*)p_w1h, (const __nv_bfloat16*)p_w1l,
            (float*)p_part, 1024, 2048, 2048, 256);
        reduce_f32<<<(256 * 1024) / 256, 256>>>((const float*)p_part, b1,
                                                (float*)p_h1, 1024, 8);
    }
    fc2_kernel<<<256, 256>>>(W2, b2);
    dmp_kernel<<<20, 256>>>(out);
}